// round 3
// baseline (speedup 1.0000x reference)
#include <cuda_runtime.h>
#include <cstdint>

// ---------------------------------------------------------------------------
// RNN_MultiRegional_SAC — persistent-kernel implementation.
// h = relu(0.9 h + 0.1 (h @ W^T + drive)), 512 steps, B=32, 3H=3072.
// W_rec has 5 nonzero 1024x1024 blocks packed in g_W: [W00=-fixed, W02, W10, W21, W22]
//   rows 0..1023:    W00 (h[0:1024])   + W02 (h[2048:3072])
//   rows 1024..2047: W10 (h[0:1024])
//   rows 2048..3071: W21 (h[1024:2048]) + W22 (h[2048:3072])
// Work partition: 640 equal quanta (8 rows x 1024 K). Phase A computes
// partial dots into g_part; Phase B (after grid barrier) combines + relu.
// Output (float32): [mean 32*512][std 32*512][hn_last 32*3072][rnn 32*512*3072]
// ---------------------------------------------------------------------------

#define Hh   1024
#define H3   3072
#define Bz   32
#define Tz   512
#define NEXC 717
#define HH   (Hh*Hh)
#define NBLK 296
#define NQ   640

__device__ __align__(128) float g_W[5u * HH];
__device__ __align__(128) float g_h[2][H3 * Bz];     // [n][b]
__device__ __align__(128) float g_part[NQ * 256];    // per-quantum partials [8 rows][32 b]
__device__ unsigned g_cnt;                            // barrier arrive counter (self-cleaning)
__device__ unsigned g_gen;                            // barrier generation (monotone)

// ---------------- helpers ----------------
__device__ __forceinline__ void fma2(unsigned long long& acc, unsigned long long a, unsigned long long b) {
    asm("fma.rn.f32x2 %0, %1, %2, %0;" : "+l"(acc) : "l"(a), "l"(b));
}
__device__ __forceinline__ void unpack2(unsigned long long v, float& x, float& y) {
    asm("mov.b64 {%0, %1}, %2;" : "=f"(x), "=f"(y) : "l"(v));
}
__device__ __forceinline__ void cp16(void* dst, const void* src) {
    unsigned d = (unsigned)__cvta_generic_to_shared(dst);
    asm volatile("cp.async.cg.shared.global [%0], [%1], 16;" :: "r"(d), "l"(src));
}
#define CP_COMMIT() asm volatile("cp.async.commit_group;")
#define CP_WAIT0()  asm volatile("cp.async.wait_group 0;")

// ---------------- prep: build packed W blocks ---------------------------------
__global__ void prep_kernel(const float* __restrict__ w_str2thal,
                            const float* __restrict__ w_m12m1,
                            const float* __restrict__ w_m12str,
                            const float* __restrict__ w_thal2m1,
                            const float* __restrict__ fixedw) {
    int idx = blockIdx.x * blockDim.x + threadIdx.x;
    if (idx >= HH) return;
    int c = idx & (Hh - 1);
    g_W[0 * HH + idx] = -fixedw[idx];
    float v = fminf(fmaxf(w_m12str[idx], 1e-10f), 1.0f);
    g_W[1 * HH + idx] = (c < NEXC) ? v : 0.0f;
    v = fminf(fmaxf(w_str2thal[idx], 1e-10f), 1.0f);
    g_W[2 * HH + idx] = (c < (Hh / 2)) ? v : -v;
    g_W[3 * HH + idx] = fminf(fmaxf(w_thal2m1[idx], 1e-10f), 1.0f);
    v = fminf(fmaxf(w_m12m1[idx], 1e-10f), 1.0f);
    g_W[4 * HH + idx] = (c < NEXC) ? v : -v;
}

// ---------------- init: hn -> g_h[0] transposed to [n][b] ---------------------
__global__ void init_kernel(const float* __restrict__ hn) {
    int idx = blockIdx.x * blockDim.x + threadIdx.x;
    if (idx >= H3 * Bz) return;
    int n = idx >> 5, b = idx & 31;
    g_h[0][idx] = hn[b * H3 + n];
}

// ---------------- persistent RNN kernel ----------------------------------------
// 296 blocks x 256 threads, all resident. Per step:
//   Phase A: each block computes 2-3 quanta (8 rows x 1024 K partial dots)
//   grid barrier
//   Phase B: combine partials + drive + relu; write hnext / rnn
//   grid barrier
__global__ void __launch_bounds__(256, 2) rnn_persist(const float* __restrict__ inp,
                                                      const float* __restrict__ inp_weight,
                                                      float* __restrict__ rnn) {
    __shared__ __align__(16) float sWd[2][8 * 132];   // pair-duplicated W: [row][2k..] pad 132
    __shared__ __align__(16) float sH[2][64 * 36];    // [k][b], pad 36
    __shared__ __align__(16) float sRed[2048];        // 8 warps x 256 partial floats

    const int tx   = threadIdx.x;
    const int bid  = blockIdx.x;
    const int lane = tx & 31;
    const int ks   = tx >> 5;          // K-split warp (0..7)
    const int rg   = lane >> 2;        // row group (0..7)
    const int bg   = lane & 3;         // b group (8 b each)
    const int wrow = ks;               // W load: warp w loads row w
    const int wcol = lane * 2;         // 2 consecutive floats

    const int qs = (bid < 48) ? 3 * bid : 2 * bid + 48;
    const int qe = qs + ((bid < 48) ? 3 : 2);

    // epilogue range: 98304 outputs over 296 blocks (332/333 each)
    const int o0  = bid * 332 + (bid < 32 ? bid : 32);
    const int ocnt = 332 + (bid < 32 ? 1 : 0);

    unsigned base;
    asm volatile("ld.volatile.global.u32 %0, [%1];" : "=r"(base) : "l"(&g_gen));
    unsigned tgt = base;

    for (int t = 0; t < Tz; t++) {
        const float* __restrict__ hprev = g_h[t & 1];
        float* __restrict__ hnext = g_h[(t + 1) & 1];

        // ================= Phase A: quanta =================
        for (int q = qs; q < qe; q++) {
            // decode quantum
            int wblk, hoff, nbase;
            if (q < 256)      { wblk = q & 1;       hoff = (q & 1) ? 2048 : 0;          nbase = (q >> 1) * 8; }
            else if (q < 384) { wblk = 2;           hoff = 0;                           nbase = 1024 + (q - 256) * 8; }
            else              { wblk = 3 + (q & 1); hoff = 1024 + (q & 1) * 1024;       nbase = 2048 + ((q - 384) >> 1) * 8; }

            const float* Wp = g_W + (size_t)wblk * HH + (size_t)(nbase & (Hh - 1)) * Hh;
            const float* Hp = hprev + hoff * Bz;

            unsigned long long acc[4] = {0ull, 0ull, 0ull, 0ull};

            // preload tile 0
            float2 w = *(const float2*)(Wp + wrow * Hh + wcol);
#pragma unroll
            for (int i = 0; i < 2; i++) {
                int c = tx + i * 256;
                cp16(&sH[0][(c >> 3) * 36 + (c & 7) * 4], Hp + c * 4);
            }
            CP_COMMIT();

            int buf = 0;
#pragma unroll 1
            for (int kt = 0; kt < 16; kt++) {
                // stage W (duplicated pairs) into current buffer
                *(float4*)&sWd[buf][wrow * 132 + wcol * 2] = make_float4(w.x, w.x, w.y, w.y);
                CP_WAIT0();
                __syncthreads();

                if (kt < 15) {
                    w = *(const float2*)(Wp + wrow * Hh + (kt + 1) * 64 + wcol);
                    const float* Hn = Hp + (kt + 1) * 64 * Bz;
#pragma unroll
                    for (int i = 0; i < 2; i++) {
                        int c = tx + i * 256;
                        cp16(&sH[buf ^ 1][(c >> 3) * 36 + (c & 7) * 4], Hn + c * 4);
                    }
                    CP_COMMIT();
                }

                // compute: 8 k per warp, processed as 4 pairs
                const float* wbase = &sWd[buf][rg * 132 + ks * 16];
                const float* hbase = &sH[buf][(ks * 8) * 36 + bg * 8];
#pragma unroll
                for (int kk = 0; kk < 4; kk++) {
                    ulonglong2 wv = *(const ulonglong2*)(wbase + kk * 4);       // (w0,w0),(w1,w1)
                    ulonglong2 ha = *(const ulonglong2*)(hbase + (kk * 2) * 36);
                    ulonglong2 hb = *(const ulonglong2*)(hbase + (kk * 2) * 36 + 4);
                    ulonglong2 hc = *(const ulonglong2*)(hbase + (kk * 2 + 1) * 36);
                    ulonglong2 hd = *(const ulonglong2*)(hbase + (kk * 2 + 1) * 36 + 4);
                    fma2(acc[0], wv.x, ha.x); fma2(acc[1], wv.x, ha.y);
                    fma2(acc[2], wv.x, hb.x); fma2(acc[3], wv.x, hb.y);
                    fma2(acc[0], wv.y, hc.x); fma2(acc[1], wv.y, hc.y);
                    fma2(acc[2], wv.y, hd.x); fma2(acc[3], wv.y, hd.y);
                }
                buf ^= 1;
            }

            // flush: cross-warp reduce 8 K-split partials, write g_part[q]
            {
                float f[8];
#pragma unroll
                for (int j = 0; j < 4; j++) unpack2(acc[j], f[j * 2], f[j * 2 + 1]);
                *(float4*)&sRed[tx * 8]     = make_float4(f[0], f[1], f[2], f[3]);
                *(float4*)&sRed[tx * 8 + 4] = make_float4(f[4], f[5], f[6], f[7]);
                __syncthreads();
                float s = 0.0f;
#pragma unroll
                for (int k2 = 0; k2 < 8; k2++) s += sRed[k2 * 256 + tx];
                g_part[q * 256 + tx] = s;
                __syncthreads();
            }
        }

        // ================= barrier =================
        __syncthreads();
        if (tx == 0) {
            __threadfence();
            ++tgt;
            if (atomicAdd(&g_cnt, 1u) == NBLK - 1) {
                g_cnt = 0;
                __threadfence();
                atomicExch(&g_gen, tgt);
            } else {
                unsigned cur;
                do {
                    __nanosleep(64);
                    asm volatile("ld.volatile.global.u32 %0, [%1];" : "=r"(cur) : "l"(&g_gen));
                } while ((int)(cur - tgt) < 0);
                __threadfence();
            }
        } else { ++tgt; }
        __syncthreads();

        // ================= Phase B: combine + relu + store =================
        for (int i = tx; i < ocnt; i += 256) {
            int o = o0 + i;
            int n = o >> 5, b = o & 31;
            int off = (n & 7) * 32 + b;
            float s;
            if (n < 1024) {
                int u = n >> 3;
                s = g_part[(2 * u) * 256 + off] + g_part[(2 * u + 1) * 256 + off];
            } else if (n < 2048) {
                s = g_part[((n >> 3) + 128) * 256 + off];
            } else {
                int u = (n >> 3) - 256;
                s = g_part[(384 + 2 * u) * 256 + off] + g_part[(384 + 2 * u + 1) * 256 + off];
            }
            float4 iv = ((const float4*)inp)[b * Tz + t];
            float d = iv.x * inp_weight[0 * H3 + n] + iv.y * inp_weight[1 * H3 + n]
                    + iv.z * inp_weight[2 * H3 + n] + iv.w * inp_weight[3 * H3 + n];
            float hp = hprev[n * Bz + b];
            float v = fmaxf(0.9f * hp + 0.1f * (s + d), 0.0f);
            hnext[n * Bz + b] = v;
            rnn[((size_t)(b * Tz + t)) * H3 + n] = v;
        }

        // ================= barrier =================
        __syncthreads();
        if (tx == 0) {
            __threadfence();
            ++tgt;
            if (atomicAdd(&g_cnt, 1u) == NBLK - 1) {
                g_cnt = 0;
                __threadfence();
                atomicExch(&g_gen, tgt);
            } else {
                unsigned cur;
                do {
                    __nanosleep(64);
                    asm volatile("ld.volatile.global.u32 %0, [%1];" : "=r"(cur) : "l"(&g_gen));
                } while ((int)(cur - tgt) < 0);
                __threadfence();
            }
        } else { ++tgt; }
        __syncthreads();
    }
}

// ---------------- heads: mean/std over masked (m1) region ---------------------
__global__ void head_kernel(const float* __restrict__ rnn,
                            const float* __restrict__ mean_w, const float* __restrict__ mean_b,
                            const float* __restrict__ std_w,  const float* __restrict__ std_b,
                            float* __restrict__ mean_out, float* __restrict__ std_out) {
    int warp = blockIdx.x * 8 + (threadIdx.x >> 5);   // = b*512 + t
    int lane = threadIdx.x & 31;
    const float* row = rnn + (size_t)warp * H3 + 2048;
    float sm = 0.0f, ss = 0.0f;
#pragma unroll 8
    for (int i = lane; i < Hh; i += 32) {
        float v = row[i];
        sm += v * mean_w[2048 + i];
        ss += v * std_w[2048 + i];
    }
#pragma unroll
    for (int off = 16; off; off >>= 1) {
        sm += __shfl_down_sync(0xFFFFFFFFu, sm, off);
        ss += __shfl_down_sync(0xFFFFFFFFu, ss, off);
    }
    if (lane == 0) {
        mean_out[warp] = sm + mean_b[0];
        float s = ss + std_b[0];
        std_out[warp] = fminf(fmaxf(s, -5.0f), 10.0f);
    }
}

// ---------------- hn_last copy -------------------------------------------------
__global__ void hn_kernel(const float* __restrict__ rnn, float* __restrict__ hn_out) {
    int idx = blockIdx.x * blockDim.x + threadIdx.x;
    if (idx >= Bz * H3) return;
    int b = idx / H3, n = idx - b * H3;
    hn_out[idx] = rnn[((size_t)(b * Tz + (Tz - 1))) * H3 + n];
}

// ---------------- launch --------------------------------------------------------
extern "C" void kernel_launch(void* const* d_in, const int* in_sizes, int n_in,
                              void* d_out, int out_size) {
    const float* inp        = (const float*)d_in[0];   // [32,512,4]
    const float* hn         = (const float*)d_in[1];   // [1,32,3072]
    // d_in[2] = w_str2str (unused: its mask is all-zeros in the reference)
    const float* w_str2thal = (const float*)d_in[3];
    const float* w_m12m1    = (const float*)d_in[4];
    const float* w_m12str   = (const float*)d_in[5];
    const float* w_thal2m1  = (const float*)d_in[6];
    const float* fixedw     = (const float*)d_in[7];
    const float* inp_weight = (const float*)d_in[8];   // [4,3072]
    const float* mean_w     = (const float*)d_in[9];   // [1,3072]
    const float* mean_b     = (const float*)d_in[10];  // [1]
    const float* std_w      = (const float*)d_in[11];
    const float* std_b      = (const float*)d_in[12];
    // d_in[13] = sampling flag

    float* out      = (float*)d_out;
    float* mean_out = out;                         // 32*512
    float* std_out  = out + 16384;                 // 32*512
    float* hn_out   = out + 32768;                 // 32*3072
    float* rnn      = out + 131072;                // 32*512*3072

    prep_kernel<<<(HH + 255) / 256, 256>>>(w_str2thal, w_m12m1, w_m12str, w_thal2m1, fixedw);
    init_kernel<<<(H3 * Bz + 255) / 256, 256>>>(hn);

    rnn_persist<<<NBLK, 256>>>(inp, inp_weight, rnn);

    head_kernel<<<2048, 256>>>(rnn, mean_w, mean_b, std_w, std_b, mean_out, std_out);
    hn_kernel<<<(Bz * H3 + 255) / 256, 256>>>(rnn, hn_out);
}

// round 4
// speedup vs baseline: 2.1021x; 2.1021x over previous
#include <cuda_runtime.h>
#include <cuda_bf16.h>
#include <cstdint>

// ---------------------------------------------------------------------------
// RNN_MultiRegional_SAC — bf16 tensor-core (mma.sync) implementation.
// h = relu(0.9 h + 0.1 (h @ W^T + drive)), 512 steps, B=32, 3H=3072.
// W_rec: 5 nonzero 1024x1024 blocks, bf16: [W00=-fixed, W02, W10, W21, W22]
//   n 0..1023:    W00 (k: h[0:1024])    + W02 (k: h[2048:3072])
//   n 1024..2047: W10 (k: h[0:1024])
//   n 2048..3071: W21 (k: h[1024:2048]) + W22 (k: h[2048:3072])
// D[b][n] = sum_k h[b][k] * W[n][k]  via mma.m16n8k16.row.col (A=h, B=W).
// fp32 master h (decay path exact); bf16 only on mma operands.
// Output (float32): [mean 32*512][std 32*512][hn_last 32*3072][rnn 32*512*3072]
// ---------------------------------------------------------------------------

#define Hh   1024
#define H3   3072
#define Bz   32
#define Tz   512
#define NEXC 717
#define HH   (Hh*Hh)

__device__ __align__(256) __nv_bfloat16 g_Wb[5u * HH];      // 10 MB
__device__ __align__(256) float         g_hf[2][Bz * H3];   // fp32 master h [b][n]
__device__ __align__(256) __nv_bfloat16 g_hb[2][Bz * H3];   // bf16 operand h [b][n]

// ---------------- helpers ----------------
__device__ __forceinline__ void cp16(void* dst, const void* src) {
    unsigned d = (unsigned)__cvta_generic_to_shared(dst);
    asm volatile("cp.async.cg.shared.global [%0], [%1], 16;" :: "r"(d), "l"(src));
}
#define CP_COMMIT() asm volatile("cp.async.commit_group;")
#define CP_WAIT0()  asm volatile("cp.async.wait_group 0;")

__device__ __forceinline__ unsigned smem_u32(const void* p) {
    return (unsigned)__cvta_generic_to_shared(p);
}

// ---------------- prep: build packed bf16 W blocks -----------------------------
__global__ void prep_kernel(const float* __restrict__ w_str2thal,
                            const float* __restrict__ w_m12m1,
                            const float* __restrict__ w_m12str,
                            const float* __restrict__ w_thal2m1,
                            const float* __restrict__ fixedw) {
    int idx = blockIdx.x * blockDim.x + threadIdx.x;
    if (idx >= HH) return;
    int c = idx & (Hh - 1);
    g_Wb[0u * HH + idx] = __float2bfloat16(-fixedw[idx]);
    float v = fminf(fmaxf(w_m12str[idx], 1e-10f), 1.0f);
    g_Wb[1u * HH + idx] = __float2bfloat16((c < NEXC) ? v : 0.0f);
    v = fminf(fmaxf(w_str2thal[idx], 1e-10f), 1.0f);
    g_Wb[2u * HH + idx] = __float2bfloat16((c < (Hh / 2)) ? v : -v);
    g_Wb[3u * HH + idx] = __float2bfloat16(fminf(fmaxf(w_thal2m1[idx], 1e-10f), 1.0f));
    v = fminf(fmaxf(w_m12m1[idx], 1e-10f), 1.0f);
    g_Wb[4u * HH + idx] = __float2bfloat16((c < NEXC) ? v : -v);
}

// ---------------- init: hn ([1][32][3072] = [b][n]) -> h masters ---------------
__global__ void init_kernel(const float* __restrict__ hn) {
    int idx = blockIdx.x * blockDim.x + threadIdx.x;
    if (idx >= Bz * H3) return;
    float v = hn[idx];
    g_hf[0][idx] = v;
    g_hb[0][idx] = __float2bfloat16(v);
}

// ---------------- per-step tensor-core kernel ----------------------------------
// Grid 96 blocks x 256 threads (8 warps).
//  bid [0,32):  region str,  n0 = bid*32,            K-segs: W00 (h 0..1K),  W02 (h 2K..3K)
//  bid [32,64): region m1,   n0 = 2048+(bid-32)*32,  K-segs: W21 (h 1K..2K), W22 (h 2K..3K)
//  bid [64,96): region thal, n0 = 1024+(bid-64)*32,  K-seg:  W10 (h 0..1K)   (16 tiles)
// Warp w: bt = w&1 (batch half), nh = w>>1 (n-octet). Each warp owns a full-K
// 16b x 8n output fragment -> no cross-warp reduction.
// K-tiles of 64, cp.async double-buffered; ldmatrix (non-trans) for A and B.
__global__ void __launch_bounds__(256) step_mma(int t,
                                                const float* __restrict__ inp,
                                                const float* __restrict__ iw,
                                                float* __restrict__ rnn) {
    __shared__ __align__(16) __nv_bfloat16 sW[2][32 * 72];   // [n][k] pad 72
    __shared__ __align__(16) __nv_bfloat16 sH[2][32 * 72];   // [b][k] pad 72

    const int tx   = threadIdx.x;
    const int bid  = blockIdx.x;
    const int wid  = tx >> 5;
    const int lane = tx & 31;
    const int cur  = t & 1, nxt = cur ^ 1;

    int n0, ntile, h0, h1;
    const __nv_bfloat16 *w0p, *w1p;
    if (bid < 32)      { n0 = bid * 32;             w0p = g_Wb;           w1p = g_Wb + 1u*HH; h0 = 0;    h1 = 2048; ntile = 32; }
    else if (bid < 64) { n0 = 2048 + (bid-32)*32;   w0p = g_Wb + 3u*HH;   w1p = g_Wb + 4u*HH; h0 = 1024; h1 = 2048; ntile = 32; }
    else               { n0 = 1024 + (bid-64)*32;   w0p = g_Wb + 2u*HH;   w1p = w0p;          h0 = 0;    h1 = 0;    ntile = 16; }
    const int nloc = n0 & (Hh - 1);

    const __nv_bfloat16* __restrict__ hb = g_hb[cur];

    // ---- ldmatrix lane addressing (within-tile element offsets) ----
    const int bt = wid & 1, nh = wid >> 1;
    const int am = lane >> 3, ai = lane & 7;
    const int arow = bt * 16 + (am & 1) * 8 + ai;   // batch row
    const int acol = (am >> 1) * 8;                  // k offset (quadrant)
    const int brow = nh * 8 + (lane & 7);            // n row
    const int bcol = ((lane >> 3) & 1) * 8;          // k offset (lanes>=16 mirror, ignored by x2)
    unsigned aoff[2], boff[2];
    aoff[0] = smem_u32(&sH[0][arow * 72 + acol]);
    aoff[1] = smem_u32(&sH[1][arow * 72 + acol]);
    boff[0] = smem_u32(&sW[0][brow * 72 + bcol]);
    boff[1] = smem_u32(&sW[1][brow * 72 + bcol]);

    // ---- staging: 512 x 16B chunks per tile, 2 per thread ----
    auto stage = [&](int kt, int bf) {
        const int seg  = kt >> 4;
        const int koff = (kt & 15) << 6;
        const __nv_bfloat16* wp = (seg ? w1p : w0p) + (size_t)nloc * Hh + koff;
        const __nv_bfloat16* hp = hb + (seg ? h1 : h0) + koff;
#pragma unroll
        for (int i = 0; i < 2; i++) {
            int c   = tx + i * 256;
            int r   = (c >> 3) & 31;
            int col = c & 7;
            if (c < 256) cp16(&sW[bf][r * 72 + col * 8], wp + r * Hh + col * 8);
            else         cp16(&sH[bf][r * 72 + col * 8], hp + (size_t)r * H3 + col * 8);
        }
        CP_COMMIT();
    };

    stage(0, 0);
    float d0 = 0.f, d1 = 0.f, d2 = 0.f, d3 = 0.f;
    int buf = 0;
#pragma unroll 1
    for (int kt = 0; kt < ntile; kt++) {
        CP_WAIT0();
        __syncthreads();
        if (kt + 1 < ntile) stage(kt + 1, buf ^ 1);

        unsigned aa = aoff[buf], bb = boff[buf];
#pragma unroll
        for (int kk = 0; kk < 4; kk++) {
            unsigned a0, a1, a2, a3, b0, b1;
            asm volatile("ldmatrix.sync.aligned.m8n8.x4.shared.b16 {%0,%1,%2,%3}, [%4];"
                         : "=r"(a0), "=r"(a1), "=r"(a2), "=r"(a3) : "r"(aa + kk * 32));
            asm volatile("ldmatrix.sync.aligned.m8n8.x2.shared.b16 {%0,%1}, [%2];"
                         : "=r"(b0), "=r"(b1) : "r"(bb + kk * 32));
            asm volatile("mma.sync.aligned.m16n8k16.row.col.f32.bf16.bf16.f32 "
                         "{%0,%1,%2,%3}, {%4,%5,%6,%7}, {%8,%9}, {%0,%1,%2,%3};"
                         : "+f"(d0), "+f"(d1), "+f"(d2), "+f"(d3)
                         : "r"(a0), "r"(a1), "r"(a2), "r"(a3), "r"(b0), "r"(b1));
        }
        buf ^= 1;
    }

    // ---- epilogue: drive + relu update; write h masters + rnn ----
    {
        const int g = lane >> 2, tg = lane & 3;
        const int ncol = n0 + nh * 8 + 2 * tg;
        float* __restrict__ hfn = g_hf[nxt];
        __nv_bfloat16* __restrict__ hbn = g_hb[nxt];
        const float* __restrict__ hfc = g_hf[cur];

        float iwv[2][4];
#pragma unroll
        for (int j = 0; j < 2; j++)
#pragma unroll
            for (int i = 0; i < 4; i++) iwv[j][i] = iw[i * H3 + ncol + j];

#pragma unroll
        for (int half = 0; half < 2; half++) {
            int b = bt * 16 + g + half * 8;
            float4 iv = ((const float4*)inp)[b * Tz + t];
            float dd0 = half ? d2 : d0;
            float dd1 = half ? d3 : d1;
#pragma unroll
            for (int j = 0; j < 2; j++) {
                int n = ncol + j;
                float s = j ? dd1 : dd0;
                float drv = iv.x * iwv[j][0] + iv.y * iwv[j][1]
                          + iv.z * iwv[j][2] + iv.w * iwv[j][3];
                float hp = hfc[b * H3 + n];
                float v = fmaxf(0.9f * hp + 0.1f * (s + drv), 0.0f);
                hfn[b * H3 + n] = v;
                hbn[b * H3 + n] = __float2bfloat16(v);
                rnn[((size_t)(b * Tz + t)) * H3 + n] = v;
            }
        }
    }
}

// ---------------- heads: mean/std over masked (m1) region ----------------------
__global__ void head_kernel(const float* __restrict__ rnn,
                            const float* __restrict__ mean_w, const float* __restrict__ mean_b,
                            const float* __restrict__ std_w,  const float* __restrict__ std_b,
                            float* __restrict__ mean_out, float* __restrict__ std_out) {
    int warp = blockIdx.x * 8 + (threadIdx.x >> 5);   // = b*512 + t
    int lane = threadIdx.x & 31;
    const float* row = rnn + (size_t)warp * H3 + 2048;
    float sm = 0.0f, ss = 0.0f;
#pragma unroll 8
    for (int i = lane; i < Hh; i += 32) {
        float v = row[i];
        sm += v * mean_w[2048 + i];
        ss += v * std_w[2048 + i];
    }
#pragma unroll
    for (int off = 16; off; off >>= 1) {
        sm += __shfl_down_sync(0xFFFFFFFFu, sm, off);
        ss += __shfl_down_sync(0xFFFFFFFFu, ss, off);
    }
    if (lane == 0) {
        mean_out[warp] = sm + mean_b[0];
        float s = ss + std_b[0];
        std_out[warp] = fminf(fmaxf(s, -5.0f), 10.0f);
    }
}

// ---------------- hn_last copy --------------------------------------------------
__global__ void hn_kernel(const float* __restrict__ rnn, float* __restrict__ hn_out) {
    int idx = blockIdx.x * blockDim.x + threadIdx.x;
    if (idx >= Bz * H3) return;
    int b = idx / H3, n = idx - b * H3;
    hn_out[idx] = rnn[((size_t)(b * Tz + (Tz - 1))) * H3 + n];
}

// ---------------- launch ---------------------------------------------------------
extern "C" void kernel_launch(void* const* d_in, const int* in_sizes, int n_in,
                              void* d_out, int out_size) {
    const float* inp        = (const float*)d_in[0];   // [32,512,4]
    const float* hn         = (const float*)d_in[1];   // [1,32,3072]
    // d_in[2] = w_str2str (unused: its mask is all-zeros in the reference)
    const float* w_str2thal = (const float*)d_in[3];
    const float* w_m12m1    = (const float*)d_in[4];
    const float* w_m12str   = (const float*)d_in[5];
    const float* w_thal2m1  = (const float*)d_in[6];
    const float* fixedw     = (const float*)d_in[7];
    const float* inp_weight = (const float*)d_in[8];   // [4,3072]
    const float* mean_w     = (const float*)d_in[9];   // [1,3072]
    const float* mean_b     = (const float*)d_in[10];  // [1]
    const float* std_w      = (const float*)d_in[11];
    const float* std_b      = (const float*)d_in[12];
    // d_in[13] = sampling flag

    float* out      = (float*)d_out;
    float* mean_out = out;                         // 32*512
    float* std_out  = out + 16384;                 // 32*512
    float* hn_out   = out + 32768;                 // 32*3072
    float* rnn      = out + 131072;                // 32*512*3072

    prep_kernel<<<(HH + 255) / 256, 256>>>(w_str2thal, w_m12m1, w_m12str, w_thal2m1, fixedw);
    init_kernel<<<(Bz * H3 + 255) / 256, 256>>>(hn);

    for (int t = 0; t < Tz; t++)
        step_mma<<<96, 256>>>(t, inp, inp_weight, rnn);

    head_kernel<<<2048, 256>>>(rnn, mean_w, mean_b, std_w, std_b, mean_out, std_out);
    hn_kernel<<<(Bz * H3 + 255) / 256, 256>>>(rnn, hn_out);
}

// round 5
// speedup vs baseline: 4.0891x; 1.9453x over previous
#include <cuda_runtime.h>
#include <cuda_bf16.h>
#include <cstdint>

// ---------------------------------------------------------------------------
// RNN_MultiRegional_SAC — bf16 mma.sync, 3-stage cp.async pipeline, K-tile 128.
// h = relu(0.9 h + 0.1 (h @ W^T + drive)), 512 steps, B=32, 3H=3072.
// W_rec: 5 nonzero 1024x1024 blocks, bf16: [W00=-fixed, W02, W10, W21, W22]
//   n 0..1023:    W00 (k: h[0:1024])    + W02 (k: h[2048:3072])
//   n 1024..2047: W10 (k: h[0:1024])
//   n 2048..3071: W21 (k: h[1024:2048]) + W22 (k: h[2048:3072])
// D[b][n] = sum_k h[b][k] * W[n][k]  via mma.m16n8k16.row.col (A=h, B=W).
// fp32 master h; bf16 only on mma operands.
// Output (float32): [mean 32*512][std 32*512][hn_last 32*3072][rnn 32*512*3072]
// ---------------------------------------------------------------------------

#define Hh   1024
#define H3   3072
#define Bz   32
#define Tz   512
#define NEXC 717
#define HH   (Hh*Hh)

__device__ __align__(256) __nv_bfloat16 g_Wb[5u * HH];      // 10 MB
__device__ __align__(256) float         g_hf[2][Bz * H3];   // fp32 master h [b][n]
__device__ __align__(256) __nv_bfloat16 g_hb[2][Bz * H3];   // bf16 operand h [b][n]

// ---------------- helpers ----------------
__device__ __forceinline__ void cp16(unsigned dst, const void* src) {
    asm volatile("cp.async.cg.shared.global [%0], [%1], 16;" :: "r"(dst), "l"(src));
}
#define CP_COMMIT() asm volatile("cp.async.commit_group;")
#define CP_WAIT1()  asm volatile("cp.async.wait_group 1;")

__device__ __forceinline__ unsigned smem_u32(const void* p) {
    return (unsigned)__cvta_generic_to_shared(p);
}

// ---------------- prep: build packed bf16 W blocks -----------------------------
__global__ void prep_kernel(const float* __restrict__ w_str2thal,
                            const float* __restrict__ w_m12m1,
                            const float* __restrict__ w_m12str,
                            const float* __restrict__ w_thal2m1,
                            const float* __restrict__ fixedw) {
    int idx = blockIdx.x * blockDim.x + threadIdx.x;
    if (idx >= HH) return;
    int c = idx & (Hh - 1);
    g_Wb[0u * HH + idx] = __float2bfloat16(-fixedw[idx]);
    float v = fminf(fmaxf(w_m12str[idx], 1e-10f), 1.0f);
    g_Wb[1u * HH + idx] = __float2bfloat16((c < NEXC) ? v : 0.0f);
    v = fminf(fmaxf(w_str2thal[idx], 1e-10f), 1.0f);
    g_Wb[2u * HH + idx] = __float2bfloat16((c < (Hh / 2)) ? v : -v);
    g_Wb[3u * HH + idx] = __float2bfloat16(fminf(fmaxf(w_thal2m1[idx], 1e-10f), 1.0f));
    v = fminf(fmaxf(w_m12m1[idx], 1e-10f), 1.0f);
    g_Wb[4u * HH + idx] = __float2bfloat16((c < NEXC) ? v : -v);
}

// ---------------- init: hn ([1][32][3072] = [b][n]) -> h masters ---------------
__global__ void init_kernel(const float* __restrict__ hn) {
    int idx = blockIdx.x * blockDim.x + threadIdx.x;
    if (idx >= Bz * H3) return;
    float v = hn[idx];
    g_hf[0][idx] = v;
    g_hb[0][idx] = __float2bfloat16(v);
}

// ---------------- per-step tensor-core kernel ----------------------------------
// Grid 96 x 256 threads (8 warps). Warp = (bt = w&1: batch half, nh = w>>1:
// n-octet); each warp owns a full-K 16b x 8n fragment (no cross-warp combine).
// K-tile 128, 3-stage cp.async pipeline, XOR-swizzled smem (chunk ^= row&7).
// Tile byte layout: row*256 + (chunk16B ^ (row&7))*16.
__global__ void __launch_bounds__(256) step_mma(int t,
                                                const float* __restrict__ inp,
                                                const float* __restrict__ iw,
                                                float* __restrict__ rnn) {
    __shared__ __align__(256) unsigned char sWb[3][8192];   // [n=32][k=128] bf16, swizzled
    __shared__ __align__(256) unsigned char sHb[3][8192];   // [b=32][k=128] bf16, swizzled

    const int tx   = threadIdx.x;
    const int bid  = blockIdx.x;
    const int wid  = tx >> 5;
    const int lane = tx & 31;
    const int cur  = t & 1, nxt = cur ^ 1;

    int n0, ntile, h0, h1;
    const __nv_bfloat16 *w0p, *w1p;
    if (bid < 32)      { n0 = bid * 32;             w0p = g_Wb;           w1p = g_Wb + 1u*HH; h0 = 0;    h1 = 2048; ntile = 16; }
    else if (bid < 64) { n0 = 2048 + (bid-32)*32;   w0p = g_Wb + 3u*HH;   w1p = g_Wb + 4u*HH; h0 = 1024; h1 = 2048; ntile = 16; }
    else               { n0 = 1024 + (bid-64)*32;   w0p = g_Wb + 2u*HH;   w1p = w0p;          h0 = 0;    h1 = 0;    ntile = 8; }
    const int nloc = n0 & (Hh - 1);

    const __nv_bfloat16* __restrict__ hb = g_hb[cur];

    // ---- ldmatrix lane addressing ----
    const int bt = wid & 1, nh = wid >> 1;
    const int am = lane >> 3, ai = lane & 7;
    const int arow = bt * 16 + (am & 1) * 8 + ai;   // batch row (A)
    const int qa   = am >> 1;                        // k quadrant (0/1)
    const int sa   = arow & 7;                       // swizzle key
    const int brow = nh * 8 + (lane & 7);            // n row (B)
    const int qb   = (lane >> 3) & 1;
    const int sb   = brow & 7;

    unsigned hbase[3], wbase[3];
#pragma unroll
    for (int s = 0; s < 3; s++) {
        hbase[s] = smem_u32(sHb[s]) + arow * 256;
        wbase[s] = smem_u32(sWb[s]) + brow * 256;
    }

    // staging bases (4 cp16 per thread: 2 W chunks, 2 H chunks)
    unsigned wdst[3], hdst[3];
    {
        int c0 = tx;                 // W chunk ids tx, tx+256
        int r0 = c0 >> 4, col0 = c0 & 15;
        (void)r0; (void)col0;
    }

    auto stage = [&](int kt, int bf) {
        const int seg  = kt >> 3;
        const int koff = (kt & 7) << 7;
        const __nv_bfloat16* wp = (seg ? w1p : w0p) + (size_t)nloc * Hh + koff;
        const __nv_bfloat16* hp = hb + (seg ? h1 : h0) + koff;
        unsigned wB = smem_u32(sWb[bf]);
        unsigned hB = smem_u32(sHb[bf]);
#pragma unroll
        for (int i = 0; i < 2; i++) {
            int c = tx + i * 256;               // chunk 0..511
            int r = c >> 4, col = c & 15;
            int ph = col ^ (r & 7);
            cp16(wB + r * 256 + ph * 16, wp + (size_t)r * Hh + col * 8);
            cp16(hB + r * 256 + ph * 16, hp + (size_t)r * H3 + col * 8);
        }
        CP_COMMIT();
    };

    stage(0, 0);
    stage(1, 1);

    float d0 = 0.f, d1 = 0.f, d2 = 0.f, d3 = 0.f;
#pragma unroll 1
    for (int kt = 0; kt < ntile; kt++) {
        CP_WAIT1();
        __syncthreads();
        if (kt + 2 < ntile) stage(kt + 2, (kt + 2) % 3);
        else CP_COMMIT();

        const int bf = kt % 3;
        const unsigned ha = hbase[bf];
        const unsigned wa = wbase[bf];
#pragma unroll
        for (int kk = 0; kk < 8; kk++) {
            unsigned a0, a1, a2, a3, b0, b1;
            unsigned aaddr = ha + (((2 * kk + qa) ^ sa) << 4);
            unsigned baddr = wa + (((2 * kk + qb) ^ sb) << 4);
            asm volatile("ldmatrix.sync.aligned.m8n8.x4.shared.b16 {%0,%1,%2,%3}, [%4];"
                         : "=r"(a0), "=r"(a1), "=r"(a2), "=r"(a3) : "r"(aaddr));
            asm volatile("ldmatrix.sync.aligned.m8n8.x2.shared.b16 {%0,%1}, [%2];"
                         : "=r"(b0), "=r"(b1) : "r"(baddr));
            asm volatile("mma.sync.aligned.m16n8k16.row.col.f32.bf16.bf16.f32 "
                         "{%0,%1,%2,%3}, {%4,%5,%6,%7}, {%8,%9}, {%0,%1,%2,%3};"
                         : "+f"(d0), "+f"(d1), "+f"(d2), "+f"(d3)
                         : "r"(a0), "r"(a1), "r"(a2), "r"(a3), "r"(b0), "r"(b1));
        }
    }

    // ---- epilogue: drive + relu update; write h masters + rnn ----
    {
        const int g = lane >> 2, tg = lane & 3;
        const int ncol = n0 + nh * 8 + 2 * tg;
        float* __restrict__ hfn = g_hf[nxt];
        __nv_bfloat16* __restrict__ hbn = g_hb[nxt];
        const float* __restrict__ hfc = g_hf[cur];

        float iwv[2][4];
#pragma unroll
        for (int j = 0; j < 2; j++)
#pragma unroll
            for (int i = 0; i < 4; i++) iwv[j][i] = iw[i * H3 + ncol + j];

#pragma unroll
        for (int half = 0; half < 2; half++) {
            int b = bt * 16 + g + half * 8;
            float4 iv = ((const float4*)inp)[b * Tz + t];
            float dd0 = half ? d2 : d0;
            float dd1 = half ? d3 : d1;
#pragma unroll
            for (int j = 0; j < 2; j++) {
                int n = ncol + j;
                float s = j ? dd1 : dd0;
                float drv = iv.x * iwv[j][0] + iv.y * iwv[j][1]
                          + iv.z * iwv[j][2] + iv.w * iwv[j][3];
                float hp = hfc[b * H3 + n];
                float v = fmaxf(0.9f * hp + 0.1f * (s + drv), 0.0f);
                hfn[b * H3 + n] = v;
                hbn[b * H3 + n] = __float2bfloat16(v);
                rnn[((size_t)(b * Tz + t)) * H3 + n] = v;
            }
        }
    }
}

// ---------------- heads: mean/std over masked (m1) region ----------------------
__global__ void head_kernel(const float* __restrict__ rnn,
                            const float* __restrict__ mean_w, const float* __restrict__ mean_b,
                            const float* __restrict__ std_w,  const float* __restrict__ std_b,
                            float* __restrict__ mean_out, float* __restrict__ std_out) {
    int warp = blockIdx.x * 8 + (threadIdx.x >> 5);   // = b*512 + t
    int lane = threadIdx.x & 31;
    const float* row = rnn + (size_t)warp * H3 + 2048;
    float sm = 0.0f, ss = 0.0f;
#pragma unroll 8
    for (int i = lane; i < Hh; i += 32) {
        float v = row[i];
        sm += v * mean_w[2048 + i];
        ss += v * std_w[2048 + i];
    }
#pragma unroll
    for (int off = 16; off; off >>= 1) {
        sm += __shfl_down_sync(0xFFFFFFFFu, sm, off);
        ss += __shfl_down_sync(0xFFFFFFFFu, ss, off);
    }
    if (lane == 0) {
        mean_out[warp] = sm + mean_b[0];
        float s = ss + std_b[0];
        std_out[warp] = fminf(fmaxf(s, -5.0f), 10.0f);
    }
}

// ---------------- hn_last copy --------------------------------------------------
__global__ void hn_kernel(const float* __restrict__ rnn, float* __restrict__ hn_out) {
    int idx = blockIdx.x * blockDim.x + threadIdx.x;
    if (idx >= Bz * H3) return;
    int b = idx / H3, n = idx - b * H3;
    hn_out[idx] = rnn[((size_t)(b * Tz + (Tz - 1))) * H3 + n];
}

// ---------------- launch ---------------------------------------------------------
extern "C" void kernel_launch(void* const* d_in, const int* in_sizes, int n_in,
                              void* d_out, int out_size) {
    const float* inp        = (const float*)d_in[0];   // [32,512,4]
    const float* hn         = (const float*)d_in[1];   // [1,32,3072]
    // d_in[2] = w_str2str (unused: its mask is all-zeros in the reference)
    const float* w_str2thal = (const float*)d_in[3];
    const float* w_m12m1    = (const float*)d_in[4];
    const float* w_m12str   = (const float*)d_in[5];
    const float* w_thal2m1  = (const float*)d_in[6];
    const float* fixedw     = (const float*)d_in[7];
    const float* inp_weight = (const float*)d_in[8];   // [4,3072]
    const float* mean_w     = (const float*)d_in[9];   // [1,3072]
    const float* mean_b     = (const float*)d_in[10];  // [1]
    const float* std_w      = (const float*)d_in[11];
    const float* std_b      = (const float*)d_in[12];
    // d_in[13] = sampling flag

    float* out      = (float*)d_out;
    float* mean_out = out;                         // 32*512
    float* std_out  = out + 16384;                 // 32*512
    float* hn_out   = out + 32768;                 // 32*3072
    float* rnn      = out + 131072;                // 32*512*3072

    prep_kernel<<<(HH + 255) / 256, 256>>>(w_str2thal, w_m12m1, w_m12str, w_thal2m1, fixedw);
    init_kernel<<<(Bz * H3 + 255) / 256, 256>>>(hn);

    for (int t = 0; t < Tz; t++)
        step_mma<<<96, 256>>>(t, inp, inp_weight, rnn);

    head_kernel<<<2048, 256>>>(rnn, mean_w, mean_b, std_w, std_b, mean_out, std_out);
    hn_kernel<<<(Bz * H3 + 255) / 256, 256>>>(rnn, hn_out);
}